// round 6
// baseline (speedup 1.0000x reference)
#include <cuda_runtime.h>
#include <math.h>

#define BATCH 2
#define CH    64
#define HH    112
#define WW    112
#define HWSZ  (HH*WW)
#define NPIX  (BATCH*HWSZ)
#define RAD   3
#define NN    49
#define NPAD  52

__device__ __align__(256) float g_px  [NPIX*CH];    // range-projected, NHWC
__device__ __align__(256) float g_spat[NPIX*CH];    // spatial feats, NHWC
__device__ __align__(256) float g_mid [NPIX*CH];    // pre-output_proj, NHWC
__device__ __align__(256) float g_fxs [NPIX*CH];    // fixup semantic partial (64-pad)
__device__ __align__(256) float g_comb[NPIX*NPAD];  // bilateral weights (52-pad)

__device__ __forceinline__ float grp16_sum(float v) {
#pragma unroll
    for (int off = 8; off > 0; off >>= 1)
        v += __shfl_xor_sync(0xffffffffu, v, off);
    return v;
}
__device__ __forceinline__ float sigmf(float x) {
    return 1.f / (1.f + __expf(-x));
}

#define FMA4W(Acc, W, X) { \
    Acc.x = fmaf(W.x, X, Acc.x); Acc.y = fmaf(W.y, X, Acc.y); \
    Acc.z = fmaf(W.z, X, Acc.z); Acc.w = fmaf(W.w, X, Acc.w); }

// LN over the 16-lane group (invn = 1/channels); returns normalized*g+be
__device__ __forceinline__ float4 ln_apply(float4 A, float4 g, float4 be, float invn) {
    float s1 = grp16_sum(A.x + A.y + A.z + A.w);
    float s2 = grp16_sum(A.x*A.x + A.y*A.y + A.z*A.z + A.w*A.w);
    float u  = s1 * invn;
    float rs = rsqrtf(fmaxf(s2 * invn - u * u, 0.f) + 1e-6f);
    return make_float4(fmaf(g.x, (A.x - u) * rs, be.x),
                       fmaf(g.y, (A.y - u) * rs, be.y),
                       fmaf(g.z, (A.z - u) * rs, be.z),
                       fmaf(g.w, (A.w - u) * rs, be.w));
}
__device__ __forceinline__ float4 silu4(float4 v) {
    return make_float4(v.x * sigmf(v.x), v.y * sigmf(v.y),
                       v.z * sigmf(v.z), v.w * sigmf(v.w));
}

// ---------------- NCHW -> NHWC transpose of spatial feats -------------------
__global__ __launch_bounds__(256) void k_transpose(const float* __restrict__ in) {
    __shared__ float t[64 * 33];
    const int blk   = blockIdx.x;
    const int b     = blk / (HWSZ / 32);
    const int pbase = (blk - b * (HWSZ / 32)) * 32;
    const float* inb = in + (size_t)b * CH * HWSZ;
    for (int i = threadIdx.x; i < 2048; i += 256) {
        int c = i >> 5, p = i & 31;
        t[c * 33 + p] = inb[c * HWSZ + pbase + p];
    }
    __syncthreads();
    float* outb = g_spat + ((size_t)b * HWSZ + pbase) * CH;
    for (int i = threadIdx.x; i < 2048; i += 256) {
        int p = i >> 6, c = i & 63;
        outb[p * CH + c] = t[c * 33 + p];
    }
}

// ---------------- range_proj + fixup-semantic GEMM --------------------------
// 128 px/block, thread = 8 px x 4 channels.
__global__ __launch_bounds__(256) void k_rangeproj(
    const float* __restrict__ sem,
    const float* __restrict__ w1, const float* __restrict__ b1,
    const float* __restrict__ gg, const float* __restrict__ be,
    const float* __restrict__ w2, const float* __restrict__ b2,
    const float* __restrict__ fxw1) {
    extern __shared__ float sm[];
    float* W1t = sm;                 // [64][68]
    float* W2t = W1t + 64 * 68;      // [64][68]
    float* Wf  = W2t + 64 * 68;      // [64][68]
    float* xs  = Wf  + 64 * 68;      // [64][128] x[c][p]; later y[p][c] stride 64
    const int tid = threadIdx.x;
    for (int i = tid; i < 4096; i += 256) {
        int o = i >> 6, c = i & 63;
        W1t[c * 68 + o] = w1[i];
        W2t[c * 68 + o] = w2[i];
        Wf [c * 68 + o] = (o < NN) ? fxw1[o * 113 + 49 + c] : 0.f;
    }
    const int oq = tid & 15, p0 = (tid >> 4) << 3;
    const float4 rb1 = *(const float4*)(b1 + oq * 4);
    const float4 rg  = *(const float4*)(gg + oq * 4);
    const float4 rbe = *(const float4*)(be + oq * 4);
    const float4 rb2 = *(const float4*)(b2 + oq * 4);

    const int pg0   = blockIdx.x << 7;
    const int b     = pg0 / HWSZ;
    const int pbase = pg0 - b * HWSZ;
    const float* inb = sem + (size_t)b * CH * HWSZ + pbase;
    for (int i = tid; i < 2048; i += 256) {
        int c = i >> 5, q4 = (i & 31) << 2;
        *(float4*)(xs + c * 128 + q4) = *(const float4*)(inb + c * HWSZ + q4);
    }
    __syncthreads();

    float4 A[8];
    // ---- fixup-semantic GEMM first (frees registers later)
#pragma unroll
    for (int j = 0; j < 8; j++) A[j] = make_float4(0.f, 0.f, 0.f, 0.f);
#pragma unroll 8
    for (int c = 0; c < 64; c++) {
        float4 wv = *(const float4*)(Wf + c * 68 + (oq << 2));
        float4 xa = *(const float4*)(xs + (c << 7) + p0);
        float4 xb = *(const float4*)(xs + (c << 7) + p0 + 4);
        FMA4W(A[0], wv, xa.x) FMA4W(A[1], wv, xa.y)
        FMA4W(A[2], wv, xa.z) FMA4W(A[3], wv, xa.w)
        FMA4W(A[4], wv, xb.x) FMA4W(A[5], wv, xb.y)
        FMA4W(A[6], wv, xb.z) FMA4W(A[7], wv, xb.w)
    }
    {
        float* fo = g_fxs + (size_t)(pg0 + p0) * CH + (oq << 2);
#pragma unroll
        for (int j = 0; j < 8; j++) *(float4*)(fo + j * CH) = A[j];
    }

    // ---- conv1
#pragma unroll
    for (int j = 0; j < 8; j++) A[j] = rb1;
#pragma unroll 8
    for (int c = 0; c < 64; c++) {
        float4 wv = *(const float4*)(W1t + c * 68 + (oq << 2));
        float4 xa = *(const float4*)(xs + (c << 7) + p0);
        float4 xb = *(const float4*)(xs + (c << 7) + p0 + 4);
        FMA4W(A[0], wv, xa.x) FMA4W(A[1], wv, xa.y)
        FMA4W(A[2], wv, xa.z) FMA4W(A[3], wv, xa.w)
        FMA4W(A[4], wv, xb.x) FMA4W(A[5], wv, xb.y)
        FMA4W(A[6], wv, xb.z) FMA4W(A[7], wv, xb.w)
    }
    // LN + SiLU in place
#pragma unroll
    for (int j = 0; j < 8; j++) A[j] = silu4(ln_apply(A[j], rg, rbe, 1.f / 64.f));
    __syncthreads();              // all xs reads (fxs + conv1) complete
#pragma unroll
    for (int j = 0; j < 8; j++)
        *(float4*)(xs + (p0 + j) * 64 + (oq << 2)) = A[j];
    __syncwarp();                 // y rows are 16-lane-group private

    // ---- conv2
    float4 Z[8];
#pragma unroll
    for (int j = 0; j < 8; j++) Z[j] = rb2;
#pragma unroll 8
    for (int c = 0; c < 64; c++) {
        float4 wv = *(const float4*)(W2t + c * 68 + (oq << 2));
#pragma unroll
        for (int j = 0; j < 8; j++) {
            float xv = xs[(p0 + j) * 64 + c];
            FMA4W(Z[j], wv, xv)
        }
    }
    {
        float* po = g_px + (size_t)(pg0 + p0) * CH + (oq << 2);
#pragma unroll
        for (int j = 0; j < 8; j++) *(float4*)(po + j * CH) = Z[j];
    }
}

// ---------------- k_weights: raw bilateral weights -> g_comb ----------------
__global__ __launch_bounds__(256) void k_weights(const float* __restrict__ sigp) {
    __shared__ float combw[8][56];
    const int tid = threadIdx.x;
    const int wid = tid >> 5, lane = tid & 31;
    const int half = lane >> 4, q = lane & 15;
    const float sigma   = *sigp;
    const float inv2sig = 0.5f / (sigma * sigma);
    float* cw = combw[wid];

    const int pg = (blockIdx.x << 3) + wid;
    const int b  = pg / HWSZ;
    const int hw = pg - b * HWSZ;
    const int h  = hw / WW, w = hw - h * WW;
    const size_t bbase = (size_t)b * HWSZ;

    const float4 cv4 = ((const float4*)(g_px + (size_t)pg * CH))[q];

    for (int k = 0; k < 25; k++) {
        const int n  = (k << 1) + half;
        const int n7 = n / 7;
        const int dy = n7 - RAD, dx = n - n7 * 7 - RAD;
        const int hh = h + dy, ww2 = w + dx;
        const bool val = (n < NN) && ((unsigned)hh < (unsigned)HH) &&
                         ((unsigned)ww2 < (unsigned)WW);
        float d = 0.f;
        if (val) {
            float4 nv = ((const float4*)(g_px + (bbase + hh * WW + ww2) * CH))[q];
            float e0 = nv.x - cv4.x, e1 = nv.y - cv4.y;
            float e2 = nv.z - cv4.z, e3 = nv.w - cv4.w;
            d = fmaf(e0, e0, fmaf(e1, e1, fmaf(e2, e2, e3 * e3)));
        }
        d = grp16_sum(d);
        if (q == 0 && n < NN) {
            float d2s = (float)(dy * dy + dx * dx);
            cw[n] = val ? __expf(-fmaf(d, 1.f / 128.f, d2s * inv2sig)) : 0.f;
        }
    }
    __syncwarp();
    float* co = g_comb + (size_t)pg * NPAD;
    co[lane] = cw[lane];
    if (lane < 20) co[32 + lane] = (lane < 17) ? cw[32 + lane] : 0.f;
}

// ---------------- k_fixup: batched fixup MLP + gate + normalize -------------
// 128 px/block, thread = 8 px x 4 outs (outs 64-padded).
__global__ __launch_bounds__(256) void k_fixup(
    const float* __restrict__ fxw1, const float* __restrict__ fxb1,
    const float* __restrict__ fxg,  const float* __restrict__ fxbe,
    const float* __restrict__ fxw2, const float* __restrict__ fxb2) {
    extern __shared__ float sm[];
    float* W1t = sm;               // [49][68]
    float* W2t = W1t + 49 * 68;    // [49][68]
    float* xsh = W2t + 49 * 68;    // [128][52]
    float* ysh = xsh + 128 * NPAD; // [128][52]
    float* sb1 = ysh + 128 * NPAD;
    float* sg  = sb1 + 64;
    float* sbe = sg  + 64;
    float* sb2 = sbe + 64;
    const int tid = threadIdx.x;
    for (int i = tid; i < 49 * 64; i += 256) {
        int n = i >> 6, o = i & 63;
        W1t[n * 68 + o] = (o < NN) ? fxw1[o * 113 + n] : 0.f;
        W2t[n * 68 + o] = (o < NN) ? fxw2[o * NN + n]  : 0.f;
    }
    if (tid < 64) {
        sb1[tid] = (tid < NN) ? fxb1[tid] : 0.f;
        sg [tid] = (tid < NN) ? fxg [tid] : 0.f;
        sbe[tid] = (tid < NN) ? fxbe[tid] : 0.f;
        sb2[tid] = (tid < NN) ? fxb2[tid] : 0.f;
    }
    const int pg0 = blockIdx.x << 7;
    const float* cin = g_comb + (size_t)pg0 * NPAD;
    for (int i = tid; i < 128 * 13; i += 256) {
        int p = i / 13, j4 = (i - p * 13) << 2;
        *(float4*)(xsh + p * NPAD + j4) = *(const float4*)(cin + p * NPAD + j4);
    }
    __syncthreads();

    const int oq = tid & 15, p0 = (tid >> 4) << 3;
    const float4 b1v = *(const float4*)(sb1 + (oq << 2));
    const float4 gv  = *(const float4*)(sg  + (oq << 2));
    const float4 bev = *(const float4*)(sbe + (oq << 2));
    const float4 b2v = *(const float4*)(sb2 + (oq << 2));

    float4 A[8];
    {
        const float* fxp = g_fxs + (size_t)(pg0 + p0) * CH + (oq << 2);
#pragma unroll
        for (int j = 0; j < 8; j++) {
            float4 F = *(const float4*)(fxp + j * CH);
            A[j] = make_float4(b1v.x + F.x, b1v.y + F.y, b1v.z + F.z, b1v.w + F.w);
        }
    }
#pragma unroll 7
    for (int n = 0; n < NN; n++) {
        float4 wv = *(const float4*)(W1t + n * 68 + (oq << 2));
#pragma unroll
        for (int j = 0; j < 8; j++) {
            float xv = xsh[(p0 + j) * NPAD + n];
            FMA4W(A[j], wv, xv)
        }
    }
    // LN(49) + SiLU, stage into ysh (guarded f4 stores)
#pragma unroll
    for (int j = 0; j < 8; j++) {
        A[j] = silu4(ln_apply(A[j], gv, bev, 1.f / 49.f));
        if (oq < 13) *(float4*)(ysh + (p0 + j) * NPAD + (oq << 2)) = A[j];
    }
    __syncwarp();

    float4 Z[8];
#pragma unroll
    for (int j = 0; j < 8; j++) Z[j] = b2v;
#pragma unroll 7
    for (int n = 0; n < NN; n++) {
        float4 wv = *(const float4*)(W2t + n * 68 + (oq << 2));
#pragma unroll
        for (int j = 0; j < 8; j++) {
            float yv = ysh[(p0 + j) * NPAD + n];
            FMA4W(Z[j], wv, yv)
        }
    }
    // gate + normalize + store
#pragma unroll
    for (int j = 0; j < 8; j++) {
        float4 C = make_float4(0.f, 0.f, 0.f, 0.f);
        if (oq < 13) C = *(const float4*)(xsh + (p0 + j) * NPAD + (oq << 2));
        C.x *= 1.f + sigmf(Z[j].x); C.y *= 1.f + sigmf(Z[j].y);
        C.z *= 1.f + sigmf(Z[j].z); C.w *= 1.f + sigmf(Z[j].w);
        float inv = 1.f / (grp16_sum(C.x + C.y + C.z + C.w) + 1e-7f);
        if (oq < 13) {
            float* co = g_comb + (size_t)(pg0 + p0 + j) * NPAD + (oq << 2);
            *(float4*)(co) = make_float4(C.x * inv, C.y * inv, C.z * inv, C.w * inv);
        }
    }
}

// ---------------- k_reduce: weighted neighborhood reduction -----------------
__global__ __launch_bounds__(256) void k_reduce() {
    __shared__ float cws[8][NPAD];
    const int tid = threadIdx.x;
    const int wid = tid >> 5, lane = tid & 31;
    const int half = lane >> 4, q = lane & 15;
    float* cw = cws[wid];

    const int pg = (blockIdx.x << 3) + wid;
    const int b  = pg / HWSZ;
    const int hw = pg - b * HWSZ;
    const int h  = hw / WW, w = hw - h * WW;
    const size_t bbase = (size_t)b * HWSZ;

    if (lane < 13)
        *(float4*)(cw + (lane << 2)) =
            *(const float4*)(g_comb + (size_t)pg * NPAD + (lane << 2));
    __syncwarp();

    float a0 = 0.f, a1 = 0.f, a2 = 0.f, a3 = 0.f;
    for (int k = 0; k < 25; k++) {
        const int n  = (k << 1) + half;
        const int n7 = n / 7;
        const int dy = n7 - RAD, dx = n - n7 * 7 - RAD;
        const int hh = h + dy, ww2 = w + dx;
        const bool val = (n < NN) && ((unsigned)hh < (unsigned)HH) &&
                         ((unsigned)ww2 < (unsigned)WW);
        if (val) {
            float cn = cw[n];
            float4 sv = ((const float4*)(g_spat + (bbase + hh * WW + ww2) * CH))[q];
            a0 = fmaf(sv.x, cn, a0); a1 = fmaf(sv.y, cn, a1);
            a2 = fmaf(sv.z, cn, a2); a3 = fmaf(sv.w, cn, a3);
        }
    }
    a0 += __shfl_xor_sync(0xffffffffu, a0, 16);
    a1 += __shfl_xor_sync(0xffffffffu, a1, 16);
    a2 += __shfl_xor_sync(0xffffffffu, a2, 16);
    a3 += __shfl_xor_sync(0xffffffffu, a3, 16);
    if (half == 0)
        ((float4*)(g_mid + (size_t)pg * CH))[q] = make_float4(a0, a1, a2, a3);
}

// ---------------- output_proj: conv1x1 -> LN -> conv1x1 ---------------------
// 128 px/block, thread = 8 px x 4 channels. g_mid NHWC -> out NCHW.
__global__ __launch_bounds__(256) void k_outproj(
    const float* __restrict__ w1, const float* __restrict__ b1,
    const float* __restrict__ gg, const float* __restrict__ be,
    const float* __restrict__ w2, const float* __restrict__ b2,
    float* __restrict__ out) {
    extern __shared__ float sm[];
    float* W1t = sm;                // [64][68]
    float* W2t = W1t + 64 * 68;     // [64][68]
    float* xsh = W2t + 64 * 68;     // [128][68] x[p][c], aliased as y after conv1
    const int tid = threadIdx.x;
    for (int i = tid; i < 4096; i += 256) {
        int o = i >> 6, c = i & 63;
        W1t[c * 68 + o] = w1[i];
        W2t[c * 68 + o] = w2[i];
    }
    const int oq = tid & 15, p0 = (tid >> 4) << 3;
    const float4 rb1 = *(const float4*)(b1 + oq * 4);
    const float4 rg  = *(const float4*)(gg + oq * 4);
    const float4 rbe = *(const float4*)(be + oq * 4);
    const float4 rb2 = *(const float4*)(b2 + oq * 4);

    const int pg0   = blockIdx.x << 7;
    const int b     = pg0 / HWSZ;
    const int pbase = pg0 - b * HWSZ;
    const float* inb = g_mid + (size_t)pg0 * CH;
    for (int i = tid; i < 2048; i += 256) {
        int p = i >> 4, cq = (i & 15) << 2;
        *(float4*)(xsh + p * 68 + cq) = *(const float4*)(inb + p * CH + cq);
    }
    __syncthreads();

    float4 A[8];
#pragma unroll
    for (int j = 0; j < 8; j++) A[j] = rb1;
#pragma unroll 8
    for (int c = 0; c < 64; c++) {
        float4 wv = *(const float4*)(W1t + c * 68 + (oq << 2));
#pragma unroll
        for (int j = 0; j < 8; j++) {
            float xv = xsh[(p0 + j) * 68 + c];
            FMA4W(A[j], wv, xv)
        }
    }
#pragma unroll
    for (int j = 0; j < 8; j++) A[j] = ln_apply(A[j], rg, rbe, 1.f / 64.f);
    __syncwarp();   // conv1 reads of this group's rows are done (rows group-private)
#pragma unroll
    for (int j = 0; j < 8; j++)
        *(float4*)(xsh + (p0 + j) * 68 + (oq << 2)) = A[j];
    __syncwarp();

    float4 Z[8];
#pragma unroll
    for (int j = 0; j < 8; j++) Z[j] = rb2;
#pragma unroll 8
    for (int c = 0; c < 64; c++) {
        float4 wv = *(const float4*)(W2t + c * 68 + (oq << 2));
#pragma unroll
        for (int j = 0; j < 8; j++) {
            float xv = xsh[(p0 + j) * 68 + c];
            FMA4W(Z[j], wv, xv)
        }
    }
    float* outb = out + (size_t)b * CH * HWSZ + (size_t)(oq * 4) * HWSZ + pbase + p0;
    *(float4*)(outb)                = make_float4(Z[0].x, Z[1].x, Z[2].x, Z[3].x);
    *(float4*)(outb + 4)            = make_float4(Z[4].x, Z[5].x, Z[6].x, Z[7].x);
    *(float4*)(outb + HWSZ)         = make_float4(Z[0].y, Z[1].y, Z[2].y, Z[3].y);
    *(float4*)(outb + HWSZ + 4)     = make_float4(Z[4].y, Z[5].y, Z[6].y, Z[7].y);
    *(float4*)(outb + 2 * HWSZ)     = make_float4(Z[0].z, Z[1].z, Z[2].z, Z[3].z);
    *(float4*)(outb + 2 * HWSZ + 4) = make_float4(Z[4].z, Z[5].z, Z[6].z, Z[7].z);
    *(float4*)(outb + 3 * HWSZ)     = make_float4(Z[0].w, Z[1].w, Z[2].w, Z[3].w);
    *(float4*)(outb + 3 * HWSZ + 4) = make_float4(Z[4].w, Z[5].w, Z[6].w, Z[7].w);
}

// ---------------- launch ----------------------------------------------------
extern "C" void kernel_launch(void* const* d_in, const int* in_sizes, int n_in,
                              void* d_out, int out_size) {
    (void)in_sizes; (void)n_in; (void)out_size;
    const float* spatial  = (const float*)d_in[0];
    const float* semantic = (const float*)d_in[1];
    const float* rp_w1 = (const float*)d_in[2];
    const float* rp_b1 = (const float*)d_in[3];
    const float* rp_g  = (const float*)d_in[4];
    const float* rp_be = (const float*)d_in[5];
    const float* rp_w2 = (const float*)d_in[6];
    const float* rp_b2 = (const float*)d_in[7];
    const float* fx_w1 = (const float*)d_in[8];
    const float* fx_b1 = (const float*)d_in[9];
    const float* fx_g  = (const float*)d_in[10];
    const float* fx_be = (const float*)d_in[11];
    const float* fx_w2 = (const float*)d_in[12];
    const float* fx_b2 = (const float*)d_in[13];
    const float* op_w1 = (const float*)d_in[14];
    const float* op_b1 = (const float*)d_in[15];
    const float* op_g  = (const float*)d_in[16];
    const float* op_be = (const float*)d_in[17];
    const float* op_w2 = (const float*)d_in[18];
    const float* op_b2 = (const float*)d_in[19];
    const float* sigma = (const float*)d_in[20];
    float* out = (float*)d_out;

    const int SMEM_RP = (3 * 64 * 68 + 64 * 128) * 4;                  // 84992 B
    const int SMEM_FX = (2 * 49 * 68 + 2 * 128 * NPAD + 4 * 64) * 4;   // 80928 B
    const int SMEM_OP = (2 * 64 * 68 + 128 * 68) * 4;                  // 69632 B
    cudaFuncSetAttribute(k_rangeproj, cudaFuncAttributeMaxDynamicSharedMemorySize, SMEM_RP);
    cudaFuncSetAttribute(k_fixup,     cudaFuncAttributeMaxDynamicSharedMemorySize, SMEM_FX);
    cudaFuncSetAttribute(k_outproj,   cudaFuncAttributeMaxDynamicSharedMemorySize, SMEM_OP);

    k_transpose<<<BATCH * (HWSZ / 32), 256>>>(spatial);
    k_rangeproj<<<NPIX / 128, 256, SMEM_RP>>>(semantic, rp_w1, rp_b1, rp_g, rp_be,
                                              rp_w2, rp_b2, fx_w1);
    k_weights<<<NPIX / 8, 256>>>(sigma);
    k_fixup<<<NPIX / 128, 256, SMEM_FX>>>(fx_w1, fx_b1, fx_g, fx_be, fx_w2, fx_b2);
    k_reduce<<<NPIX / 8, 256>>>();
    k_outproj<<<NPIX / 128, 256, SMEM_OP>>>(op_w1, op_b1, op_g, op_be,
                                            op_w2, op_b2, out);
}